// round 4
// baseline (speedup 1.0000x reference)
#include <cuda_runtime.h>
#include <math.h>

// Problem constants (fixed by setup_inputs)
#define BB   32
#define AA   3
#define HH   64
#define WW   64
#define CC   80
#define PRED_LAST 85
#define NT   2048
#define CELLS (BB*AA*HH*WW)   // 393216

#define THREADS_A 256
#define BLOCKS_A  256          // 256 blocks * 8 warps = 2048 targets
#define CPT       6            // 65536 threads * 6 = 393216 cells
#define NTHREADS_TOT (BLOCKS_A*THREADS_A)

// Zero-initialized device scratch. The last block of k_main resets every
// touched mask cell and the counter => identical state before each replay.
__device__ int    g_mask[CELLS];        // bit0=obj, bit1=kz, bit2=cross-applied
__device__ int    g_list[NT*4];         // claimed cells (or -1), 4 slots/target
__device__ double g_pconf[BLOCKS_A];
__device__ double g_pcls [BLOCKS_A];
__device__ double g_pxywh[BLOCKS_A];
__device__ int    g_pcnt [BLOCKS_A];    // (n_obj<<20)|(n_kz<<10)|n_cross
__device__ unsigned int g_done;         // block-completion counter

__device__ __forceinline__ float softplusf(float x) {
    return fmaxf(x, 0.0f) + log1pf(expf(-fabsf(x)));
}
__device__ __forceinline__ float wsumf(float v) {
    #pragma unroll
    for (int o = 16; o > 0; o >>= 1) v += __shfl_down_sync(0xFFFFFFFFu, v, o);
    return v;
}
__device__ __forceinline__ int wsumi(int v) {
    #pragma unroll
    for (int o = 16; o > 0; o >>= 1) v += __shfl_down_sync(0xFFFFFFFFu, v, o);
    return v;
}

// ---------------------------------------------------------------------------
// Single fused kernel.
//   - every thread streams 6 conf-base cells (batched gathers, MLP=6)
//   - every warp owns one target: IoU argmax, order-independent mask claims
//     with conf corrections, xywh MSE, 80-ch cls BCE
//   - last finishing block: mask reset + final reduction + loss write
// ---------------------------------------------------------------------------
__global__ void __launch_bounds__(THREADS_A) k_main(const float* __restrict__ pred,
                                                    const float* __restrict__ target,
                                                    const float* __restrict__ anchors,
                                                    float* __restrict__ out)
{
    const int tid  = threadIdx.x;
    const int lane = tid & 31;
    const int wrp  = tid >> 5;
    const int tgid = blockIdx.x * THREADS_A + tid;   // 0..65535
    const int wgid = blockIdx.x * 8 + wrp;           // 0..2047 == target id

    // ---- conf base stream (independent batched gathers) ----
    float pcv[CPT];
    #pragma unroll
    for (int k = 0; k < CPT; ++k)
        pcv[k] = __ldg(pred + (tgid + k * NTHREADS_TOT) * PRED_LAST + 4);

    // ---- target work ----
    const float* t = target + wgid * 6;
    const float tb = __ldg(t + 0);
    const float tl = __ldg(t + 1);
    const float tx = __ldg(t + 2) * (float)HH;
    const float ty = __ldg(t + 3) * (float)HH;
    const float tw = __ldg(t + 4) * (float)HH;
    const float th = __ldg(t + 5) * (float)HH;
    const int b   = (int)tb;
    const int lab = (int)tl;
    const int wi  = (int)tw;
    const int hi  = (int)th;

    float ious[AA];
    float best = -1.0f;
    int   besta = 0;
    #pragma unroll
    for (int a = 0; a < AA; ++a) {
        const float aw = __ldg(anchors + 2*a), ah = __ldg(anchors + 2*a + 1);
        const float inter = fminf(aw, tw) * fminf(ah, th);
        const float iou = inter / (aw*ah + tw*th - inter);
        ious[a] = iou;
        if (iou > best) { best = iou; besta = a; }
    }
    const int cell_best = ((b*AA + besta)*HH + hi)*WW + wi;
    const float* prow = pred + cell_best * PRED_LAST;

    // conf base partial
    float conf = 0.0f;
    #pragma unroll
    for (int k = 0; k < CPT; ++k) conf += softplusf(pcv[k]);

    // ---- claims + corrections (lanes 0-2: kz per anchor, lane 3: obj+xywh)
    float xywh = 0.0f;
    int n_obj = 0, n_kz = 0, n_cross = 0;
    int list_val = -1;

    if (lane < 3) {
        if (ious[lane] > 0.5f) {
            const int c = ((b*AA + lane)*HH + hi)*WW + wi;
            const float pc = __ldg(pred + c * PRED_LAST + 4);
            const int old = atomicOr(&g_mask[c], 2);
            if (!(old & 2)) {
                conf -= softplusf(pc);
                n_kz = 1; list_val = c;
                if (old & 1) {      // later of the (obj,kz) pair applies cross
                    const int o2 = atomicOr(&g_mask[c], 4);
                    if (!(o2 & 4)) { conf += softplusf(pc); n_cross = 1; }
                }
            }
        }
    } else if (lane == 3) {
        const int c = cell_best;
        const float pc = __ldg(prow + 4);
        const int old = atomicOr(&g_mask[c], 1);
        if (!(old & 1)) {
            conf -= pc;
            n_obj = 1; list_val = c;
            if (old & 2) {
                const int o2 = atomicOr(&g_mask[c], 4);
                if (!(o2 & 4)) { conf += softplusf(pc); n_cross = 1; }
            }
        }
        const float fx = tx - floorf(tx);
        const float fy = ty - floorf(ty);
        const float lw = logf(tw / __ldg(anchors + 2*besta));
        const float lh = logf(th / __ldg(anchors + 2*besta + 1));
        const float d0 = prow[0] - fx, d1 = prow[1] - fy;
        const float d2 = prow[2] - lw, d3 = prow[3] - lh;
        xywh = d0*d0 + d1*d1 + d2*d2 + d3*d3;
    }
    if (lane < 4) g_list[wgid*4 + lane] = list_val;   // every slot rewritten

    // ---- cls BCE over one-hot (80 channels across the warp) ----
    const float* pcls = prow + 5;
    const float x0 = __ldg(pcls + lane);
    const float x1 = __ldg(pcls + lane + 32);
    const float x2 = (lane < 16) ? __ldg(pcls + lane + 64) : 0.0f;
    float cls = softplusf(x0) + softplusf(x1);
    if (lane < 16) cls += softplusf(x2);
    if (lab < 32)      { if (lane == lab)      cls -= x0; }
    else if (lab < 64) { if (lane == lab - 32) cls -= x1; }
    else               { if (lane == lab - 64) cls -= x2; }

    // ---- block reduction -> per-block partials ----
    conf = wsumf(conf);
    cls  = wsumf(cls);
    xywh = wsumf(xywh);
    int cnt = wsumi((n_obj << 20) | (n_kz << 10) | n_cross);

    __shared__ float sc[8], sl[8], sx[8];
    __shared__ int   si[8];
    if (lane == 0) { sc[wrp] = conf; sl[wrp] = cls; sx[wrp] = xywh; si[wrp] = cnt; }
    __syncthreads();
    if (tid == 0) {
        double dc = 0.0, dl = 0.0, dx = 0.0; int ci = 0;
        #pragma unroll
        for (int w = 0; w < 8; ++w) { dc += (double)sc[w]; dl += (double)sl[w]; dx += (double)sx[w]; ci += si[w]; }
        g_pconf[blockIdx.x] = dc;
        g_pcls [blockIdx.x] = dl;
        g_pxywh[blockIdx.x] = dx;
        g_pcnt [blockIdx.x] = ci;
    }

    // ---- last-block-done finalize ----
    __threadfence();           // make this block's list + partial stores visible
    __syncthreads();
    __shared__ int is_last;
    if (tid == 0) {
        const unsigned v = atomicAdd(&g_done, 1u);
        is_last = (v == BLOCKS_A - 1u);
    }
    __syncthreads();
    if (!is_last) return;
    __threadfence();           // acquire: see all other blocks' stores

    // reset touched mask cells (batched independent loads, MLP-covered)
    const volatile int* vlist = (const volatile int*)g_list;
    #pragma unroll
    for (int i = tid; i < NT*4; i += THREADS_A) {
        const int c = vlist[i];
        if (c >= 0) g_mask[c] = 0;
    }

    // reduce the 256 per-block partials (one per thread)
    const volatile double* vpc = (const volatile double*)g_pconf;
    const volatile double* vpl = (const volatile double*)g_pcls;
    const volatile double* vpx = (const volatile double*)g_pxywh;
    const volatile int*    vpi = (const volatile int*)g_pcnt;
    double dc = vpc[tid];
    double dl = vpl[tid];
    double dx = vpx[tid];
    long long ci = (long long)vpi[tid];

    #pragma unroll
    for (int o = 16; o > 0; o >>= 1) {
        dc += __shfl_down_sync(0xFFFFFFFFu, dc, o);
        dl += __shfl_down_sync(0xFFFFFFFFu, dl, o);
        dx += __shfl_down_sync(0xFFFFFFFFu, dx, o);
        ci += __shfl_down_sync(0xFFFFFFFFu, ci, o);
    }
    __shared__ double wc[8], wl[8], wx[8];
    __shared__ long long wn[8];
    if (lane == 0) { wc[wrp] = dc; wl[wrp] = dl; wx[wrp] = dx; wn[wrp] = ci; }
    __syncthreads();

    if (tid == 0) {
        double c = 0.0, l = 0.0, x = 0.0; long long n = 0;
        #pragma unroll
        for (int w = 0; w < 8; ++w) { c += wc[w]; l += wl[w]; x += wx[w]; n += wn[w]; }
        const long long nobj   = (n >> 20) & 0xFFFFF;
        const long long nkz    = (n >> 10) & 0x3FF;
        const long long ncross =  n        & 0x3FF;
        const double n_noobj = (double)CELLS - (double)nobj - (double)nkz + (double)ncross;
        const double loss = x / ((double)NT * 4.0)
                          + c / ((double)nobj + n_noobj)
                          + l / ((double)NT * (double)CC);
        out[0] = (float)loss;
        g_done = 0;            // restore counter for next replay
    }
}

extern "C" void kernel_launch(void* const* d_in, const int* in_sizes, int n_in,
                              void* d_out, int out_size)
{
    const float* pred    = (const float*)d_in[0];
    const float* target  = (const float*)d_in[1];
    const float* anchors = (const float*)d_in[2];
    float* out = (float*)d_out;

    k_main<<<BLOCKS_A, THREADS_A>>>(pred, target, anchors, out);
}

// round 5
// speedup vs baseline: 1.3067x; 1.3067x over previous
#include <cuda_runtime.h>
#include <math.h>

// Problem constants (fixed by setup_inputs)
#define BB   32
#define AA   3
#define HH   64
#define WW   64
#define CC   80
#define PRED_LAST 85
#define NT   2048
#define CELLS (BB*AA*HH*WW)   // 393216

#define THREADS_A 256
#define BLOCKS_A  512                    // 512*4 target-warps = 2048 = NT
#define CPT       3                      // 131072 threads * 3 = 393216 cells
#define NTHREADS_TOT (BLOCKS_A*THREADS_A)

// Epoch-tagged claim words: g_mask[c] = (epoch<<3)|bits, bit0=obj, bit1=kz,
// bit2=cross. Words from older epochs read as "no bits" -> NO reset pass ever.
// g_epoch is bumped by the last block for the next launch. Output is
// identical on every call (harness requirement); only internal tags evolve.
__device__ int      g_mask[CELLS];
__device__ unsigned g_epoch;
__device__ unsigned g_done;
__device__ double g_pconf[BLOCKS_A];
__device__ double g_pcls [BLOCKS_A];
__device__ double g_pxywh[BLOCKS_A];
__device__ int    g_pcnt [BLOCKS_A];     // (n_obj<<20)|(n_kz<<10)|n_cross

__device__ __forceinline__ float softplusf(float x) {
    return fmaxf(x, 0.0f) + log1pf(expf(-fabsf(x)));
}
__device__ __forceinline__ float wsumf(float v) {
    #pragma unroll
    for (int o = 16; o > 0; o >>= 1) v += __shfl_down_sync(0xFFFFFFFFu, v, o);
    return v;
}
__device__ __forceinline__ int wsumi(int v) {
    #pragma unroll
    for (int o = 16; o > 0; o >>= 1) v += __shfl_down_sync(0xFFFFFFFFu, v, o);
    return v;
}

// Claim `bit` on cell c for this epoch; returns the bits present BEFORE the
// claim (0 if the word was from an older epoch). CAS loop; contention is
// limited to duplicate targets (rare).
__device__ __forceinline__ int claim_bits(int c, int bit, unsigned epoch) {
    int* addr = &g_mask[c];
    const unsigned tag = epoch << 3;
    unsigned old = (unsigned)*addr;
    while (true) {
        const unsigned cur = ((old >> 3) == epoch) ? (old & 7u) : 0u;
        const unsigned nv  = tag | cur | (unsigned)bit;
        const unsigned got = (unsigned)atomicCAS(addr, (int)old, (int)nv);
        if (got == old) return (int)cur;
        old = got;
    }
}

// ---------------------------------------------------------------------------
// Single fused kernel.
//   - every thread streams 3 conf-base cells (batched gathers)
//   - warps 0-3 of each block each own one target: IoU argmax, epoch-tagged
//     claims with order-independent conf corrections, xywh MSE, cls BCE
//   - last finishing block: reduce 512 partials, write loss, bump epoch
// ---------------------------------------------------------------------------
__global__ void __launch_bounds__(THREADS_A) k_main(const float* __restrict__ pred,
                                                    const float* __restrict__ target,
                                                    const float* __restrict__ anchors,
                                                    float* __restrict__ out)
{
    const int tid  = threadIdx.x;
    const int lane = tid & 31;
    const int wrp  = tid >> 5;
    const int tgid = blockIdx.x * THREADS_A + tid;   // 0..131071
    const unsigned epoch = g_epoch;                  // stable during the launch

    // ---- conf base stream (independent batched gathers) ----
    float pcv[CPT];
    #pragma unroll
    for (int k = 0; k < CPT; ++k)
        pcv[k] = __ldg(pred + (tgid + k * NTHREADS_TOT) * PRED_LAST + 4);

    float conf = 0.0f;
    #pragma unroll
    for (int k = 0; k < CPT; ++k) conf += softplusf(pcv[k]);

    float cls = 0.0f, xywh = 0.0f;
    int n_obj = 0, n_kz = 0, n_cross = 0;

    if (wrp < 4) {
        // ---- target work: one warp per target ----
        const int n = blockIdx.x * 4 + wrp;          // 0..2047
        const float* t = target + n * 6;
        const float tb = __ldg(t + 0);
        const float tl = __ldg(t + 1);
        const float tx = __ldg(t + 2) * (float)HH;
        const float ty = __ldg(t + 3) * (float)HH;
        const float tw = __ldg(t + 4) * (float)HH;
        const float th = __ldg(t + 5) * (float)HH;
        const int b   = (int)tb;
        const int lab = (int)tl;
        const int wi  = (int)tw;
        const int hi  = (int)th;

        float ious[AA];
        float best = -1.0f;
        int   besta = 0;
        #pragma unroll
        for (int a = 0; a < AA; ++a) {
            const float aw = __ldg(anchors + 2*a), ah = __ldg(anchors + 2*a + 1);
            const float inter = fminf(aw, tw) * fminf(ah, th);
            const float iou = inter / (aw*ah + tw*th - inter);
            ious[a] = iou;
            if (iou > best) { best = iou; besta = a; }
        }
        const int cell_best = ((b*AA + besta)*HH + hi)*WW + wi;
        const float* prow = pred + cell_best * PRED_LAST;

        // claims + corrections (lanes 0-2: kz per anchor, lane 3: obj+xywh)
        if (lane < 3) {
            if (ious[lane] > 0.5f) {
                const int c = ((b*AA + lane)*HH + hi)*WW + wi;
                const float pc = __ldg(pred + c * PRED_LAST + 4);
                const int prev = claim_bits(c, 2, epoch);
                if (!(prev & 2)) {
                    conf -= softplusf(pc);
                    n_kz = 1;
                    if (prev & 1) {     // later of the (obj,kz) pair applies cross
                        const int p2 = claim_bits(c, 4, epoch);
                        if (!(p2 & 4)) { conf += softplusf(pc); n_cross = 1; }
                    }
                }
            }
        } else if (lane == 3) {
            const int c = cell_best;
            const float pc = __ldg(prow + 4);
            const int prev = claim_bits(c, 1, epoch);
            if (!(prev & 1)) {
                conf -= pc;
                n_obj = 1;
                if (prev & 2) {
                    const int p2 = claim_bits(c, 4, epoch);
                    if (!(p2 & 4)) { conf += softplusf(pc); n_cross = 1; }
                }
            }
            const float fx = tx - floorf(tx);
            const float fy = ty - floorf(ty);
            const float lw = logf(tw / __ldg(anchors + 2*besta));
            const float lh = logf(th / __ldg(anchors + 2*besta + 1));
            const float d0 = prow[0] - fx, d1 = prow[1] - fy;
            const float d2 = prow[2] - lw, d3 = prow[3] - lh;
            xywh = d0*d0 + d1*d1 + d2*d2 + d3*d3;
        }

        // cls BCE over one-hot (80 channels across the warp)
        const float* pcls = prow + 5;
        const float x0 = __ldg(pcls + lane);
        const float x1 = __ldg(pcls + lane + 32);
        const float x2 = (lane < 16) ? __ldg(pcls + lane + 64) : 0.0f;
        cls = softplusf(x0) + softplusf(x1);
        if (lane < 16) cls += softplusf(x2);
        if (lab < 32)      { if (lane == lab)      cls -= x0; }
        else if (lab < 64) { if (lane == lab - 32) cls -= x1; }
        else               { if (lane == lab - 64) cls -= x2; }
    }

    // ---- block reduction -> per-block partials ----
    conf = wsumf(conf);
    cls  = wsumf(cls);
    xywh = wsumf(xywh);
    int cnt = wsumi((n_obj << 20) | (n_kz << 10) | n_cross);

    __shared__ float sc[8], sl[8], sx[8];
    __shared__ int   si[8];
    if (lane == 0) { sc[wrp] = conf; sl[wrp] = cls; sx[wrp] = xywh; si[wrp] = cnt; }
    __syncthreads();
    if (tid == 0) {
        double dc = 0.0, dl = 0.0, dx = 0.0; int ci = 0;
        #pragma unroll
        for (int w = 0; w < 8; ++w) { dc += (double)sc[w]; dl += (double)sl[w]; dx += (double)sx[w]; ci += si[w]; }
        g_pconf[blockIdx.x] = dc;
        g_pcls [blockIdx.x] = dl;
        g_pxywh[blockIdx.x] = dx;
        g_pcnt [blockIdx.x] = ci;
    }

    // ---- last-block-done finalize (reduce only; no mask reset needed) ----
    __threadfence();
    __syncthreads();
    __shared__ int is_last;
    if (tid == 0) {
        const unsigned v = atomicAdd(&g_done, 1u);
        is_last = (v == BLOCKS_A - 1u);
    }
    __syncthreads();
    if (!is_last) return;
    __threadfence();   // acquire all other blocks' partial stores

    const volatile double* vpc = (const volatile double*)g_pconf;
    const volatile double* vpl = (const volatile double*)g_pcls;
    const volatile double* vpx = (const volatile double*)g_pxywh;
    const volatile int*    vpi = (const volatile int*)g_pcnt;

    double dc = vpc[tid] + vpc[tid + 256];
    double dl = vpl[tid] + vpl[tid + 256];
    double dx = vpx[tid] + vpx[tid + 256];
    long long ci = (long long)vpi[tid] + (long long)vpi[tid + 256];

    #pragma unroll
    for (int o = 16; o > 0; o >>= 1) {
        dc += __shfl_down_sync(0xFFFFFFFFu, dc, o);
        dl += __shfl_down_sync(0xFFFFFFFFu, dl, o);
        dx += __shfl_down_sync(0xFFFFFFFFu, dx, o);
        ci += __shfl_down_sync(0xFFFFFFFFu, ci, o);
    }
    __shared__ double wc[8], wl[8], wx[8];
    __shared__ long long wn[8];
    if (lane == 0) { wc[wrp] = dc; wl[wrp] = dl; wx[wrp] = dx; wn[wrp] = ci; }
    __syncthreads();

    if (tid == 0) {
        double c = 0.0, l = 0.0, x = 0.0; long long n = 0;
        #pragma unroll
        for (int w = 0; w < 8; ++w) { c += wc[w]; l += wl[w]; x += wx[w]; n += wn[w]; }
        const long long nobj   = (n >> 20) & 0xFFFFF;
        const long long nkz    = (n >> 10) & 0x3FF;
        const long long ncross =  n        & 0x3FF;
        const double n_noobj = (double)CELLS - (double)nobj - (double)nkz + (double)ncross;
        const double loss = x / ((double)NT * 4.0)
                          + c / ((double)nobj + n_noobj)
                          + l / ((double)NT * (double)CC);
        out[0] = (float)loss;
        g_epoch = epoch + 1;   // fresh epoch for the next launch (no mask reset)
        g_done = 0;
    }
}

extern "C" void kernel_launch(void* const* d_in, const int* in_sizes, int n_in,
                              void* d_out, int out_size)
{
    const float* pred    = (const float*)d_in[0];
    const float* target  = (const float*)d_in[1];
    const float* anchors = (const float*)d_in[2];
    float* out = (float*)d_out;

    k_main<<<BLOCKS_A, THREADS_A>>>(pred, target, anchors, out);
}

// round 6
// speedup vs baseline: 1.6165x; 1.2371x over previous
#include <cuda_runtime.h>
#include <math.h>

// Problem constants (fixed by setup_inputs)
#define BB   32
#define AA   3
#define HH   64
#define WW   64
#define CC   80
#define PRED_LAST 85
#define NT   2048
#define CELLS (BB*AA*HH*WW)   // 393216

#define THREADS_A 128
#define BLOCKS_A  512          // 512*4 warps = 2048 = NT; 65536 threads
#define CPT       6            // 65536 * 6 = 393216 cells
#define NTHREADS_TOT (BLOCKS_A*THREADS_A)

// Zero-initialized device scratch. kernel B resets every touched mask cell;
// all other arrays are fully overwritten each call => replay-deterministic.
__device__ int    g_mask[CELLS];        // bit0=obj, bit1=kz, bit2=cross-applied
__device__ int    g_list[NT*4];         // claimed cells (or -1), 4 slots/target
__device__ double g_pconf[BLOCKS_A];
__device__ double g_pcls [BLOCKS_A];
__device__ double g_pxywh[BLOCKS_A];
__device__ int    g_pcnt [BLOCKS_A];    // (n_obj<<20)|(n_kz<<10)|n_cross

__device__ __forceinline__ float softplusf(float x) {
    return fmaxf(x, 0.0f) + log1pf(expf(-fabsf(x)));
}
__device__ __forceinline__ float wsumf(float v) {
    #pragma unroll
    for (int o = 16; o > 0; o >>= 1) v += __shfl_down_sync(0xFFFFFFFFu, v, o);
    return v;
}
__device__ __forceinline__ int wsumi(int v) {
    #pragma unroll
    for (int o = 16; o > 0; o >>= 1) v += __shfl_down_sync(0xFFFFFFFFu, v, o);
    return v;
}

// ---------------------------------------------------------------------------
// Kernel A (identical to the measured-fast R3 body):
//   - every thread streams 6 conf-base cells (MLP=6 gathers)
//   - every warp owns one target: IoU argmax, order-independent mask claims
//     with conf corrections, xywh MSE, 80-ch cls BCE
// ---------------------------------------------------------------------------
__global__ void __launch_bounds__(THREADS_A) k_main(const float* __restrict__ pred,
                                                    const float* __restrict__ target,
                                                    const float* __restrict__ anchors)
{
    const int tid  = threadIdx.x;
    const int lane = tid & 31;
    const int wrp  = tid >> 5;
    const int tgid = blockIdx.x * THREADS_A + tid;   // 0..65535
    const int wgid = blockIdx.x * 4 + wrp;           // 0..2047 == target id

    // ---- conf base stream (batched loads, independent of everything) ----
    float pcv[CPT];
    #pragma unroll
    for (int k = 0; k < CPT; ++k)
        pcv[k] = __ldg(pred + (tgid + k * NTHREADS_TOT) * PRED_LAST + 4);

    // ---- target work ----
    const float* t = target + wgid * 6;
    const float tb = __ldg(t + 0);
    const float tl = __ldg(t + 1);
    const float tx = __ldg(t + 2) * (float)HH;
    const float ty = __ldg(t + 3) * (float)HH;
    const float tw = __ldg(t + 4) * (float)HH;
    const float th = __ldg(t + 5) * (float)HH;
    const int b   = (int)tb;
    const int lab = (int)tl;
    const int wi  = (int)tw;
    const int hi  = (int)th;

    float ious[AA];
    float best = -1.0f;
    int   besta = 0;
    #pragma unroll
    for (int a = 0; a < AA; ++a) {
        const float aw = __ldg(anchors + 2*a), ah = __ldg(anchors + 2*a + 1);
        const float inter = fminf(aw, tw) * fminf(ah, th);
        const float iou = inter / (aw*ah + tw*th - inter);
        ious[a] = iou;
        if (iou > best) { best = iou; besta = a; }
    }
    const int cell_best = ((b*AA + besta)*HH + hi)*WW + wi;
    const float* prow = pred + cell_best * PRED_LAST;

    // conf base partial
    float conf = 0.0f;
    #pragma unroll
    for (int k = 0; k < CPT; ++k) conf += softplusf(pcv[k]);

    // ---- claims + corrections (lanes 0-2: kz per anchor, lane 3: obj+xywh)
    float xywh = 0.0f;
    int n_obj = 0, n_kz = 0, n_cross = 0;
    int list_val = -1;

    if (lane < 3) {
        if (ious[lane] > 0.5f) {
            const int c = ((b*AA + lane)*HH + hi)*WW + wi;
            const float pc = __ldg(pred + c * PRED_LAST + 4);
            const int old = atomicOr(&g_mask[c], 2);
            if (!(old & 2)) {
                conf -= softplusf(pc);
                n_kz = 1; list_val = c;
                if (old & 1) {      // I'm the later of the (obj,kz) pair
                    const int o2 = atomicOr(&g_mask[c], 4);
                    if (!(o2 & 4)) { conf += softplusf(pc); n_cross = 1; }
                }
            }
        }
    } else if (lane == 3) {
        const int c = cell_best;
        const float pc = __ldg(prow + 4);
        const int old = atomicOr(&g_mask[c], 1);
        if (!(old & 1)) {
            conf -= pc;
            n_obj = 1; list_val = c;
            if (old & 2) {
                const int o2 = atomicOr(&g_mask[c], 4);
                if (!(o2 & 4)) { conf += softplusf(pc); n_cross = 1; }
            }
        }
        // xywh MSE
        const float fx = tx - floorf(tx);
        const float fy = ty - floorf(ty);
        const float lw = logf(tw / __ldg(anchors + 2*besta));
        const float lh = logf(th / __ldg(anchors + 2*besta + 1));
        const float d0 = prow[0] - fx, d1 = prow[1] - fy;
        const float d2 = prow[2] - lw, d3 = prow[3] - lh;
        xywh = d0*d0 + d1*d1 + d2*d2 + d3*d3;
    }
    if (lane < 4) g_list[wgid*4 + lane] = list_val;   // all slots written each call

    // ---- cls BCE over one-hot (80 channels across the warp) ----
    const float* pcls = prow + 5;
    const float x0 = __ldg(pcls + lane);
    const float x1 = __ldg(pcls + lane + 32);
    const float x2 = (lane < 16) ? __ldg(pcls + lane + 64) : 0.0f;
    float cls = softplusf(x0) + softplusf(x1);
    if (lane < 16) cls += softplusf(x2);
    if (lab < 32)      { if (lane == lab)      cls -= x0; }
    else if (lab < 64) { if (lane == lab - 32) cls -= x1; }
    else               { if (lane == lab - 64) cls -= x2; }

    // ---- block reduction -> per-block partials (no global atomics) ----
    conf = wsumf(conf);
    cls  = wsumf(cls);
    xywh = wsumf(xywh);
    int cnt = wsumi((n_obj << 20) | (n_kz << 10) | n_cross);

    __shared__ float sc[4], sl[4], sx[4];
    __shared__ int   si[4];
    if (lane == 0) { sc[wrp] = conf; sl[wrp] = cls; sx[wrp] = xywh; si[wrp] = cnt; }
    __syncthreads();
    if (tid == 0) {
        double dc = 0.0, dl = 0.0, dx = 0.0; int ci = 0;
        #pragma unroll
        for (int w = 0; w < 4; ++w) { dc += (double)sc[w]; dl += (double)sl[w]; dx += (double)sx[w]; ci += si[w]; }
        g_pconf[blockIdx.x] = dc;
        g_pcls [blockIdx.x] = dl;
        g_pxywh[blockIdx.x] = dx;
        g_pcnt [blockIdx.x] = ci;
    }
}

// ---------------------------------------------------------------------------
// Kernel B (PARALLEL finalize): blocks 0-31 reset the touched mask cells
// (one list entry per thread, fully parallel); block 32 reduces the 512
// per-block partials and writes the loss. The two halves are independent.
// ---------------------------------------------------------------------------
__global__ void __launch_bounds__(256) k_final(float* __restrict__ out)
{
    const int tid = threadIdx.x;

    if (blockIdx.x < 32) {
        // 32 blocks * 256 threads = 8192 = NT*4 list entries, one each
        const int c = g_list[blockIdx.x * 256 + tid];
        if (c >= 0) g_mask[c] = 0;
        return;
    }

    // block 32: reduce 512 partials (2 per thread)
    double dc = g_pconf[tid] + g_pconf[tid + 256];
    double dl = g_pcls [tid] + g_pcls [tid + 256];
    double dx = g_pxywh[tid] + g_pxywh[tid + 256];
    long long ci = (long long)g_pcnt[tid] + (long long)g_pcnt[tid + 256];

    #pragma unroll
    for (int o = 16; o > 0; o >>= 1) {
        dc += __shfl_down_sync(0xFFFFFFFFu, dc, o);
        dl += __shfl_down_sync(0xFFFFFFFFu, dl, o);
        dx += __shfl_down_sync(0xFFFFFFFFu, dx, o);
        ci += __shfl_down_sync(0xFFFFFFFFu, ci, o);
    }
    __shared__ double wc[8], wl[8], wx[8];
    __shared__ long long wn[8];
    const int lane = tid & 31, wrp = tid >> 5;
    if (lane == 0) { wc[wrp] = dc; wl[wrp] = dl; wx[wrp] = dx; wn[wrp] = ci; }
    __syncthreads();

    if (tid == 0) {
        double c = 0.0, l = 0.0, x = 0.0; long long n = 0;
        #pragma unroll
        for (int w = 0; w < 8; ++w) { c += wc[w]; l += wl[w]; x += wx[w]; n += wn[w]; }
        const long long nobj   = (n >> 20) & 0xFFFFF;
        const long long nkz    = (n >> 10) & 0x3FF;
        const long long ncross =  n        & 0x3FF;
        const double n_noobj = (double)CELLS - (double)nobj - (double)nkz + (double)ncross;
        const double loss = x / ((double)NT * 4.0)
                          + c / ((double)nobj + n_noobj)
                          + l / ((double)NT * (double)CC);
        out[0] = (float)loss;
    }
}

extern "C" void kernel_launch(void* const* d_in, const int* in_sizes, int n_in,
                              void* d_out, int out_size)
{
    const float* pred    = (const float*)d_in[0];
    const float* target  = (const float*)d_in[1];
    const float* anchors = (const float*)d_in[2];
    float* out = (float*)d_out;

    k_main<<<BLOCKS_A, THREADS_A>>>(pred, target, anchors);
    k_final<<<33, 256>>>(out);
}

// round 7
// speedup vs baseline: 1.6933x; 1.0475x over previous
#include <cuda_runtime.h>
#include <math.h>

// Problem constants (fixed by setup_inputs)
#define BB   32
#define AA   3
#define HH   64
#define WW   64
#define CC   80
#define PRED_LAST 85          // 5 + C
#define NT   2048
#define CELLS (BB*AA*HH*WW)   // 393216

#define TGT_BLOCKS 256        // 256 blocks * 8 warps = 2048 targets
#define CONF_THREADS 256
#define CONF_BLOCKS  192      // 49152 threads * 8 cells = 393216

// Zero-initialized device scratch. k_conf resets the byte masks in-pass;
// all partial arrays are fully rewritten every call => replay-deterministic.
__device__ unsigned char g_obj[CELLS];       // obj mask
__device__ unsigned char g_kz[CELLS];        // "keep product is zero" flag
__device__ double g_tp_cls [TGT_BLOCKS];     // per-block cls partials
__device__ double g_tp_xywh[TGT_BLOCKS];     // per-block xywh partials
__device__ double g_cp_conf[CONF_BLOCKS];    // per-block conf partials
__device__ int    g_cp_cnt [CONF_BLOCKS];    // (n_obj<<16)|n_noobj per block

__device__ __forceinline__ float softplusf(float x) {
    return fmaxf(x, 0.0f) + log1pf(expf(-fabsf(x)));
}
__device__ __forceinline__ float wsumf(float v) {
    #pragma unroll
    for (int o = 16; o > 0; o >>= 1) v += __shfl_down_sync(0xFFFFFFFFu, v, o);
    return v;
}
__device__ __forceinline__ int wsumi(int v) {
    #pragma unroll
    for (int o = 16; o > 0; o >>= 1) v += __shfl_down_sync(0xFFFFFFFFu, v, o);
    return v;
}
__device__ __forceinline__ long long wsumll(long long v) {
    #pragma unroll
    for (int o = 16; o > 0; o >>= 1) v += __shfl_down_sync(0xFFFFFFFFu, v, o);
    return v;
}

// ---------------------------------------------------------------------------
// Kernel 1: one WARP per target; 8 targets per 256-thread block.
// NO global atomics: per-block partials only.
// ---------------------------------------------------------------------------
__global__ void k_targets(const float* __restrict__ pred,
                          const float* __restrict__ target,
                          const float* __restrict__ anchors)
{
    const int tid  = threadIdx.x;
    const int lane = tid & 31;
    const int wrp  = tid >> 5;
    const int n    = blockIdx.x * 8 + wrp;

    const float* t = target + n * 6;
    const float tb = __ldg(t + 0);
    const float tl = __ldg(t + 1);
    const float tx = __ldg(t + 2) * (float)HH;
    const float ty = __ldg(t + 3) * (float)HH;
    const float tw = __ldg(t + 4) * (float)HH;
    const float th = __ldg(t + 5) * (float)HH;

    const int b   = (int)tb;
    const int lab = (int)tl;
    const int wi  = (int)tw;   // grid indices come from WH in the reference
    const int hi  = (int)th;

    // IoU vs 3 anchors; argmax with first-max tie-break (strict >)
    float ious[AA];
    float best = -1.0f;
    int   besta = 0;
    #pragma unroll
    for (int a = 0; a < AA; ++a) {
        const float aw = __ldg(anchors + 2*a), ah = __ldg(anchors + 2*a + 1);
        const float inter = fminf(aw, tw) * fminf(ah, th);
        const float iou = inter / (aw*ah + tw*th - inter);
        ious[a] = iou;
        if (iou > best) { best = iou; besta = a; }
    }

    const int cell_best = ((b*AA + besta)*HH + hi)*WW + wi;
    const float* prow = pred + (long long)cell_best * PRED_LAST;

    float xywh = 0.0f;
    if (lane == 0) {
        #pragma unroll
        for (int a = 0; a < AA; ++a) {
            if (ious[a] > 0.5f) g_kz[((b*AA + a)*HH + hi)*WW + wi] = 1;
        }
        g_obj[cell_best] = 1;

        const float fx = tx - floorf(tx);
        const float fy = ty - floorf(ty);
        const float lw = logf(tw / __ldg(anchors + 2*besta));
        const float lh = logf(th / __ldg(anchors + 2*besta + 1));
        const float d0 = prow[0] - fx, d1 = prow[1] - fy;
        const float d2 = prow[2] - lw, d3 = prow[3] - lh;
        xywh = d0*d0 + d1*d1 + d2*d2 + d3*d3;
    }

    // cls BCE over one-hot: 80 channels -> lanes handle c, c+32, c+64
    const float* pcls = prow + 5;
    const float x0 = __ldg(pcls + lane);
    const float x1 = __ldg(pcls + lane + 32);
    const float x2 = (lane < 16) ? __ldg(pcls + lane + 64) : 0.0f;

    float s = softplusf(x0) + softplusf(x1);
    if (lane < 16) s += softplusf(x2);
    if (lab < 32)      { if (lane == lab)      s -= x0; }
    else if (lab < 64) { if (lane == lab - 32) s -= x1; }
    else               { if (lane == lab - 64) s -= x2; }

    s = wsumf(s);   // lane 0 holds warp cls sum

    __shared__ float scl[8];
    __shared__ float sxy[8];
    if (lane == 0) { scl[wrp] = s; sxy[wrp] = xywh; }
    __syncthreads();
    if (tid == 0) {
        float cs = 0.0f, xs = 0.0f;
        #pragma unroll
        for (int w = 0; w < 8; ++w) { cs += scl[w]; xs += sxy[w]; }
        g_tp_cls [blockIdx.x] = (double)cs;
        g_tp_xywh[blockIdx.x] = (double)xs;
    }
}

// ---------------------------------------------------------------------------
// Kernel 2: full-grid conf term, 8 cells per thread (batched loads => MLP=8).
// Reads + resets the masks in the same pass. Per-block partials, no atomics.
// ---------------------------------------------------------------------------
__global__ void __launch_bounds__(CONF_THREADS) k_conf(const float* __restrict__ pred)
{
    const int base   = blockIdx.x * CONF_THREADS + threadIdx.x;
    const int stride = CONF_BLOCKS * CONF_THREADS;   // 49152

    float pc[8];
    unsigned char o[8], kz[8];
    #pragma unroll
    for (int k = 0; k < 8; ++k) {
        const int c = base + k * stride;
        pc[k] = __ldg(pred + c * PRED_LAST + 4);
    }
    #pragma unroll
    for (int k = 0; k < 8; ++k) {
        const int c = base + k * stride;
        o[k]  = g_obj[c];
        kz[k] = g_kz[c];
    }

    float conf = 0.0f;
    int n_o = 0, n_n = 0;
    #pragma unroll
    for (int k = 0; k < 8; ++k) {
        const int c = base + k * stride;
        if (o[k] | kz[k]) { g_obj[c] = 0; g_kz[c] = 0; }   // reset touched cells
        const float sp = softplusf(pc[k]);
        if (o[k])        { conf += sp - pc[k]; n_o++; }     // bce(pc, 1)
        else if (!kz[k]) { conf += sp;         n_n++; }     // bce(pc, 0)
    }

    conf = wsumf(conf);
    int cnt = wsumi((n_o << 16) | n_n);   // per-warp: n_o<=256, n_n<=256 -> safe

    __shared__ float sc[8];
    __shared__ int   si[8];
    const int lane = threadIdx.x & 31, wrp = threadIdx.x >> 5;
    if (lane == 0) { sc[wrp] = conf; si[wrp] = cnt; }
    __syncthreads();
    if (threadIdx.x == 0) {
        float cs = 0.0f; int ci = 0;
        #pragma unroll
        for (int w = 0; w < 8; ++w) { cs += sc[w]; ci += si[w]; }
        g_cp_conf[blockIdx.x] = (double)cs;   // per-block: n_o,n_n <= 2048 -> fits
        g_cp_cnt [blockIdx.x] = ci;
    }
}

// ---------------------------------------------------------------------------
// Kernel 3: one block reduces 256+256+192+192 small partials, writes loss.
// Counts unpacked to 64-bit BEFORE reduction (sum of n_noobj overflows 16b).
// ---------------------------------------------------------------------------
__global__ void __launch_bounds__(256) k_final(float* __restrict__ out)
{
    const int tid = threadIdx.x;

    double dcls = g_tp_cls [tid];
    double dxy  = g_tp_xywh[tid];
    double dcf  = 0.0;
    long long no = 0, nn = 0;
    if (tid < CONF_BLOCKS) {
        dcf = g_cp_conf[tid];
        const int c = g_cp_cnt[tid];
        no = (long long)(c >> 16);
        nn = (long long)(c & 0xFFFF);
    }
    long long cnt = (no << 24) | nn;   // 64-bit packing: fields can't overflow now

    #pragma unroll
    for (int o = 16; o > 0; o >>= 1) {
        dcls += __shfl_down_sync(0xFFFFFFFFu, dcls, o);
        dxy  += __shfl_down_sync(0xFFFFFFFFu, dxy,  o);
        dcf  += __shfl_down_sync(0xFFFFFFFFu, dcf,  o);
        cnt  += __shfl_down_sync(0xFFFFFFFFu, cnt,  o);
    }
    __shared__ double wc[8], wx[8], wf[8];
    __shared__ long long wn[8];
    const int lane = tid & 31, wrp = tid >> 5;
    if (lane == 0) { wc[wrp] = dcls; wx[wrp] = dxy; wf[wrp] = dcf; wn[wrp] = cnt; }
    __syncthreads();

    if (tid == 0) {
        double cls = 0.0, xywh = 0.0, conf = 0.0; long long n = 0;
        #pragma unroll
        for (int w = 0; w < 8; ++w) { cls += wc[w]; xywh += wx[w]; conf += wf[w]; n += wn[w]; }
        const double n_obj   = (double)(n >> 24);
        const double n_noobj = (double)(n & 0xFFFFFF);
        out[0] = (float)(xywh / ((double)NT * 4.0)
                       + conf / (n_obj + n_noobj)
                       + cls  / ((double)NT * (double)CC));
    }
}

extern "C" void kernel_launch(void* const* d_in, const int* in_sizes, int n_in,
                              void* d_out, int out_size)
{
    const float* pred    = (const float*)d_in[0];
    const float* target  = (const float*)d_in[1];
    const float* anchors = (const float*)d_in[2];
    float* out = (float*)d_out;

    k_targets<<<TGT_BLOCKS, 256>>>(pred, target, anchors);
    k_conf<<<CONF_BLOCKS, CONF_THREADS>>>(pred);
    k_final<<<1, 256>>>(out);
}